// round 1
// baseline (speedup 1.0000x reference)
#include <cuda_runtime.h>
#include <math.h>

#define NROWS 16384
#define DK    2048
#define DOUT  2048

#define BM 128
#define BN 64
#define BK 16
#define APAD 4
#define BPAD 4

// scratch (no allocations allowed): partial stats + fused norm params
__device__ float g_psum[64][DK];
__device__ float g_psq [64][DK];
__device__ float g_scale[DK];
__device__ float g_shift[DK];

__global__ void colstats_partial(const float* __restrict__ x) {
    int col = blockIdx.x * 256 + threadIdx.x;
    int r0  = blockIdx.y * 256;
    const float* p = x + (size_t)r0 * DK + col;
    float s = 0.f, ss = 0.f;
#pragma unroll 8
    for (int r = 0; r < 256; ++r) {
        float v = p[(size_t)r * DK];
        s  += v;
        ss += v * v;
    }
    g_psum[blockIdx.y][col] = s;
    g_psq [blockIdx.y][col] = ss;
}

__global__ void colstats_final(const float* __restrict__ gamma,
                               const float* __restrict__ beta) {
    int col = blockIdx.x * 256 + threadIdx.x;
    float s = 0.f, ss = 0.f;
#pragma unroll
    for (int c = 0; c < 64; ++c) {
        s  += g_psum[c][col];
        ss += g_psq [c][col];
    }
    float mean = s / (float)NROWS;
    // unbiased variance (torch.std ddof=1); var_sqrt_i = 1/sqrt(std^2 + eps)
    float var  = (ss - s * mean) / (float)(NROWS - 1);
    float inv  = rsqrtf(var + 1e-8f);
    float sc   = gamma[col] * inv;
    g_scale[col] = sc;
    g_shift[col] = beta[col] - mean * sc;
}

__device__ __forceinline__ float clamp_small(float t) {
    const float EPS = 1e-12f;
    if (t >= 0.f && t <  EPS) return  EPS;
    if (t <  0.f && t > -EPS) return -EPS;
    return t;
}

__global__ __launch_bounds__(256, 2)
void fused_dual_gemm(const float* __restrict__ x,
                     const float* __restrict__ w1, const float* __restrict__ b1,
                     const float* __restrict__ w2, const float* __restrict__ b2,
                     float* __restrict__ out) {
    __shared__ float As [BK][BM + APAD];
    __shared__ float B1s[BK][BN + BPAD];
    __shared__ float B2s[BK][BN + BPAD];

    const int tid = threadIdx.x;
    const int tx  = tid & 15;   // N micro index (4 cols)
    const int ty  = tid >> 4;   // M micro index (8 rows)
    const int m0  = blockIdx.y * BM;
    const int n0  = blockIdx.x * BN;

    const float* xblk  = x  + (size_t)m0 * DK;
    const float* w1blk = w1 + (size_t)n0 * DK;
    const float* w2blk = w2 + (size_t)n0 * DK;

    float acc1[8][4];
    float acc2[8][4];
#pragma unroll
    for (int i = 0; i < 8; ++i)
#pragma unroll
        for (int j = 0; j < 4; ++j) { acc1[i][j] = 0.f; acc2[i][j] = 0.f; }

    const int browB = tid >> 2;   // 0..63
    const int bcgB  = tid & 3;    // 0..3

    for (int k0 = 0; k0 < DK; k0 += BK) {
        __syncthreads();
        // ---- load A tile (normalize on the fly), store K-transposed ----
#pragma unroll
        for (int i = 0; i < 2; ++i) {
            int f   = tid + 256 * i;          // 0..511 float4 slots
            int row = f >> 2;                 // 0..127
            int cg  = f & 3;                  // 0..3
            int kb  = cg * 4;
            float4 v  = *(const float4*)(xblk + (size_t)row * DK + k0 + kb);
            float4 sc = *(const float4*)(g_scale + k0 + kb);
            float4 sh = *(const float4*)(g_shift + k0 + kb);
            As[kb + 0][row] = v.x * sc.x + sh.x;
            As[kb + 1][row] = v.y * sc.y + sh.y;
            As[kb + 2][row] = v.z * sc.z + sh.z;
            As[kb + 3][row] = v.w * sc.w + sh.w;
        }
        // ---- load both B tiles ----
        {
            int kb = bcgB * 4;
            float4 v1 = *(const float4*)(w1blk + (size_t)browB * DK + k0 + kb);
            float4 v2 = *(const float4*)(w2blk + (size_t)browB * DK + k0 + kb);
            B1s[kb + 0][browB] = v1.x; B1s[kb + 1][browB] = v1.y;
            B1s[kb + 2][browB] = v1.z; B1s[kb + 3][browB] = v1.w;
            B2s[kb + 0][browB] = v2.x; B2s[kb + 1][browB] = v2.y;
            B2s[kb + 2][browB] = v2.z; B2s[kb + 3][browB] = v2.w;
        }
        __syncthreads();

#pragma unroll
        for (int kk = 0; kk < BK; ++kk) {
            float4 a0  = *(const float4*)&As [kk][ty * 8];
            float4 a1  = *(const float4*)&As [kk][ty * 8 + 4];
            float4 p1  = *(const float4*)&B1s[kk][tx * 4];
            float4 p2  = *(const float4*)&B2s[kk][tx * 4];
            float a[8] = {a0.x, a0.y, a0.z, a0.w, a1.x, a1.y, a1.z, a1.w};
            float c1[4] = {p1.x, p1.y, p1.z, p1.w};
            float c2[4] = {p2.x, p2.y, p2.z, p2.w};
#pragma unroll
            for (int i = 0; i < 8; ++i) {
#pragma unroll
                for (int j = 0; j < 4; ++j) {
                    acc1[i][j] = fmaf(a[i], c1[j], acc1[i][j]);
                    acc2[i][j] = fmaf(a[i], c2[j], acc2[i][j]);
                }
            }
        }
    }

    // ---- epilogue: bias + sigmoid + clamp + product, float4 stores ----
    float bias1[4], bias2[4];
#pragma unroll
    for (int j = 0; j < 4; ++j) {
        bias1[j] = b1[n0 + tx * 4 + j];
        bias2[j] = b2[n0 + tx * 4 + j];
    }
#pragma unroll
    for (int i = 0; i < 8; ++i) {
        float4 r;
        float* rp = (float*)&r;
#pragma unroll
        for (int j = 0; j < 4; ++j) {
            float h1 = acc1[i][j] + bias1[j];
            float z  = acc2[i][j] + bias2[j];
            float h2 = 1.0f / (1.0f + expf(-z));
            h1 = clamp_small(h1);
            h2 = clamp_small(h2);
            rp[j] = h1 * h2;
        }
        size_t row = (size_t)(m0 + ty * 8 + i);
        *(float4*)(out + row * DOUT + n0 + tx * 4) = r;
    }
}

extern "C" void kernel_launch(void* const* d_in, const int* in_sizes, int n_in,
                              void* d_out, int out_size) {
    const float* x     = (const float*)d_in[0];
    const float* w1    = (const float*)d_in[1];
    const float* b1    = (const float*)d_in[2];
    const float* w2    = (const float*)d_in[3];
    const float* b2    = (const float*)d_in[4];
    const float* gamma = (const float*)d_in[5];
    const float* beta  = (const float*)d_in[6];
    float* out = (float*)d_out;

    dim3 gridStats(DK / 256, NROWS / 256);
    colstats_partial<<<gridStats, 256>>>(x);
    colstats_final<<<DK / 256, 256>>>(gamma, beta);

    dim3 gridGemm(DOUT / BN, NROWS / BM);
    fused_dual_gemm<<<gridGemm, 256>>>(x, w1, b1, w2, b2, out);
}

// round 3
// speedup vs baseline: 2.4684x; 2.4684x over previous
#include <cuda_runtime.h>
#include <cuda_bf16.h>
#include <math.h>
#include <stdint.h>

#define NROWS 16384
#define DK    2048
#define DOUT  2048

// GEMM tiling
#define BM 128
#define BN 64
#define BKS 32                 // k elements per stage
#define NST 4                  // pipeline stages
#define ATILE_B (BM * 64)      // 8192 B  (128 rows x 32 bf16 = 64B rows)
#define WTILE_B (BN * 64)      // 4096 B
#define STAGE_B (2 * ATILE_B + 4 * WTILE_B)   // 32768
#define SMEM_BYTES_G (NST * STAGE_B)          // 131072
#define NSTAGES_K (DK / BKS)   // 64

// ---------------- device scratch (no allocations allowed) ----------------
__device__ float g_psum[64][DK];
__device__ float g_psq [64][DK];
__device__ float g_scale[DK];
__device__ float g_shift[DK];

__device__ uint4 g_Ah[(size_t)NROWS * DK / 8];
__device__ uint4 g_Al[(size_t)NROWS * DK / 8];
__device__ uint4 g_W1h[(size_t)DOUT * DK / 8];
__device__ uint4 g_W1l[(size_t)DOUT * DK / 8];
__device__ uint4 g_W2h[(size_t)DOUT * DK / 8];
__device__ uint4 g_W2l[(size_t)DOUT * DK / 8];

// ---------------- helpers ----------------
__device__ __forceinline__ uint32_t smem_u32(const void* p) {
    uint32_t a;
    asm("{ .reg .u64 t; cvta.to.shared.u64 t, %1; cvt.u32.u64 %0, t; }" : "=r"(a) : "l"(p));
    return a;
}
#define CP16(dst, src) \
    asm volatile("cp.async.cg.shared.global [%0], [%1], 16;" :: "r"(dst), "l"(src))
#define CP_COMMIT() asm volatile("cp.async.commit_group;" ::: "memory")
#define CP_WAIT2()  asm volatile("cp.async.wait_group 2;" ::: "memory")
#define CP_WAIT0()  asm volatile("cp.async.wait_group 0;" ::: "memory")

// swizzled offset inside a tile with 64B rows: chunk c (16B) XOR'ed by row bits
__device__ __forceinline__ uint32_t swz(int row, int c) {
    return (uint32_t)(row * 64 + ((c ^ ((row >> 1) & 3)) << 4));
}

__device__ __forceinline__ void ldsm4(uint32_t* r, uint32_t addr) {
    asm volatile("ldmatrix.sync.aligned.m8n8.x4.shared.b16 {%0,%1,%2,%3}, [%4];"
                 : "=r"(r[0]), "=r"(r[1]), "=r"(r[2]), "=r"(r[3]) : "r"(addr));
}

__device__ __forceinline__ void mma16816(float* d, const uint32_t* a, const uint32_t* b) {
    asm volatile(
        "mma.sync.aligned.m16n8k16.row.col.f32.bf16.bf16.f32 "
        "{%0,%1,%2,%3}, {%4,%5,%6,%7}, {%8,%9}, {%0,%1,%2,%3};"
        : "+f"(d[0]), "+f"(d[1]), "+f"(d[2]), "+f"(d[3])
        : "r"(a[0]), "r"(a[1]), "r"(a[2]), "r"(a[3]), "r"(b[0]), "r"(b[1]));
}

// A-style ldmatrix address: mat bit0 -> +8 rows, bit1 -> +k8 chunk
__device__ __forceinline__ uint32_t addrA(uint32_t tbase, int rowbase, int c0, int lid) {
    int m = lid >> 3, r8 = lid & 7;
    int row = rowbase + r8 + (m & 1) * 8;
    int ch  = c0 + (m >> 1);
    return tbase + swz(row, ch);
}
// B-style ldmatrix address: mat bit0 -> +k8 chunk, bit1 -> +8 rows
__device__ __forceinline__ uint32_t addrB(uint32_t tbase, int rowbase, int c0, int lid) {
    int m = lid >> 3, r8 = lid & 7;
    int row = rowbase + r8 + (m >> 1) * 8;
    int ch  = c0 + (m & 1);
    return tbase + swz(row, ch);
}

// ---------------- stats ----------------
__global__ void colstats_partial(const float* __restrict__ x) {
    int col = blockIdx.x * 256 + threadIdx.x;
    int r0  = blockIdx.y * 256;
    const float* p = x + (size_t)r0 * DK + col;
    float s = 0.f, ss = 0.f;
#pragma unroll 8
    for (int r = 0; r < 256; ++r) {
        float v = p[(size_t)r * DK];
        s += v; ss += v * v;
    }
    g_psum[blockIdx.y][col] = s;
    g_psq [blockIdx.y][col] = ss;
}

__global__ void colstats_final(const float* __restrict__ gamma,
                               const float* __restrict__ beta) {
    int col = blockIdx.x * 256 + threadIdx.x;
    float s = 0.f, ss = 0.f;
#pragma unroll
    for (int c = 0; c < 64; ++c) { s += g_psum[c][col]; ss += g_psq[c][col]; }
    float mean = s / (float)NROWS;
    float var  = (ss - s * mean) / (float)(NROWS - 1);   // ddof=1 (torch.std)
    float inv  = rsqrtf(var + 1e-8f);
    float sc   = gamma[col] * inv;
    g_scale[col] = sc;
    g_shift[col] = beta[col] - mean * sc;
}

// ---------------- bf16 hi/lo conversion ----------------
__device__ __forceinline__ uint32_t pack_hi(float a, float b, uint32_t& lo_out) {
    __nv_bfloat16 ha = __float2bfloat16_rn(a);
    __nv_bfloat16 hb = __float2bfloat16_rn(b);
    __nv_bfloat16 la = __float2bfloat16_rn(a - __bfloat162float(ha));
    __nv_bfloat16 lb = __float2bfloat16_rn(b - __bfloat162float(hb));
    __nv_bfloat162 hp = __halves2bfloat162(ha, hb);
    __nv_bfloat162 lp = __halves2bfloat162(la, lb);
    lo_out = *reinterpret_cast<uint32_t*>(&lp);
    return *reinterpret_cast<uint32_t*>(&hp);
}

__global__ void convert_x_kernel(const float* __restrict__ x) {
    int i = blockIdx.x * 256 + threadIdx.x;            // uint4 index (8 elems)
    int col = (i * 8) & (DK - 1);
    const float4* xp = (const float4*)x + (size_t)i * 2;
    float4 v0 = xp[0], v1 = xp[1];
    float4 sc0 = *(const float4*)(g_scale + col);
    float4 sc1 = *(const float4*)(g_scale + col + 4);
    float4 sh0 = *(const float4*)(g_shift + col);
    float4 sh1 = *(const float4*)(g_shift + col + 4);
    float a[8] = {
        v0.x * sc0.x + sh0.x, v0.y * sc0.y + sh0.y,
        v0.z * sc0.z + sh0.z, v0.w * sc0.w + sh0.w,
        v1.x * sc1.x + sh1.x, v1.y * sc1.y + sh1.y,
        v1.z * sc1.z + sh1.z, v1.w * sc1.w + sh1.w };
    uint4 hi, lo;
    hi.x = pack_hi(a[0], a[1], lo.x);
    hi.y = pack_hi(a[2], a[3], lo.y);
    hi.z = pack_hi(a[4], a[5], lo.z);
    hi.w = pack_hi(a[6], a[7], lo.w);
    g_Ah[i] = hi;
    g_Al[i] = lo;
}

__global__ void convert_w_kernel(const float* __restrict__ w, int which) {
    int i = blockIdx.x * 256 + threadIdx.x;
    const float4* wp = (const float4*)w + (size_t)i * 2;
    float4 v0 = wp[0], v1 = wp[1];
    float a[8] = {v0.x, v0.y, v0.z, v0.w, v1.x, v1.y, v1.z, v1.w};
    uint4 hi, lo;
    hi.x = pack_hi(a[0], a[1], lo.x);
    hi.y = pack_hi(a[2], a[3], lo.y);
    hi.z = pack_hi(a[4], a[5], lo.z);
    hi.w = pack_hi(a[6], a[7], lo.w);
    if (which == 0) { g_W1h[i] = hi; g_W1l[i] = lo; }
    else            { g_W2h[i] = hi; g_W2l[i] = lo; }
}

__device__ __forceinline__ float clamp_small(float t) {
    const float EPS = 1e-12f;
    if (t >= 0.f && t <  EPS) return  EPS;
    if (t <  0.f && t > -EPS) return -EPS;
    return t;
}

// ---------------- fused dual GEMM (mma.sync bf16, 3-term split) ----------------
__global__ __launch_bounds__(256, 1)
void dual_gemm_mma(const float* __restrict__ b1v, const float* __restrict__ b2v,
                   float* __restrict__ out) {
    extern __shared__ __align__(128) char smem[];
    const uint32_t sbase = smem_u32(smem);

    const int tid = threadIdx.x;
    const int lid = tid & 31;
    const int wid = tid >> 5;
    const int wm  = wid & 3;        // 4 warps along M
    const int wn  = wid >> 2;       // 2 warps along N

    // rasterize: 8 n-tiles per group, m fastest -> wave shares A rows & W cols in L2
    const int id  = blockIdx.x;
    const int grp = id >> 10;               // / (128*8)
    const int rem = id & 1023;
    const int m0  = (rem >> 3) * BM;
    const int n0  = ((grp << 3) | (rem & 7)) * BN;

    const char* srcA[2] = { (const char*)g_Ah + (size_t)m0 * 4096,
                            (const char*)g_Al + (size_t)m0 * 4096 };
    const char* srcW[4] = { (const char*)g_W1h + (size_t)n0 * 4096,
                            (const char*)g_W1l + (size_t)n0 * 4096,
                            (const char*)g_W2h + (size_t)n0 * 4096,
                            (const char*)g_W2l + (size_t)n0 * 4096 };

    // per-thread cp.async coordinates
    const int arow0 = tid >> 2;        // 0..63 (A uses two passes: +64)
    const int ac    = tid & 3;
    const int wrow  = tid >> 2;        // 0..63
    const int wc    = tid & 3;

    // issue one stage: buffer bi, k byte offset kb
    auto issue = [&](int bi, int kb) {
        const uint32_t st = sbase + bi * STAGE_B;
#pragma unroll
        for (int j = 0; j < 2; ++j) {
            int row = arow0 + 64 * j;
            uint32_t d = st + swz(row, ac);
            const char* sA = srcA[0] + (size_t)row * 4096 + kb + ac * 16;
            CP16(d, sA);
            const char* sAl = srcA[1] + (size_t)row * 4096 + kb + ac * 16;
            CP16(d + ATILE_B, sAl);
        }
        {
            uint32_t d = st + 2 * ATILE_B + swz(wrow, wc);
            const size_t off = (size_t)wrow * 4096 + kb + wc * 16;
            CP16(d,                 srcW[0] + off);
            CP16(d + WTILE_B,       srcW[1] + off);
            CP16(d + 2 * WTILE_B,   srcW[2] + off);
            CP16(d + 3 * WTILE_B,   srcW[3] + off);
        }
    };

    float acc1[2][4][4];
    float acc2[2][4][4];
#pragma unroll
    for (int mi = 0; mi < 2; ++mi)
#pragma unroll
        for (int ni = 0; ni < 4; ++ni)
#pragma unroll
            for (int j = 0; j < 4; ++j) { acc1[mi][ni][j] = 0.f; acc2[mi][ni][j] = 0.f; }

    // prologue
    issue(0, 0);   CP_COMMIT();
    issue(1, 64);  CP_COMMIT();
    issue(2, 128); CP_COMMIT();

    for (int i = 0; i < NSTAGES_K; ++i) {
        CP_WAIT2();
        __syncthreads();
        if (i + 3 < NSTAGES_K) issue((i + 3) & 3, (i + 3) * 64);
        CP_COMMIT();

        const uint32_t st  = sbase + (i & 3) * STAGE_B;
        const uint32_t stW = st + 2 * ATILE_B;
#pragma unroll
        for (int ks = 0; ks < 2; ++ks) {
            const int c0 = ks * 2;
            uint32_t ah[2][4], al[2][4];
            ldsm4(ah[0], addrA(st,            wm * 32,      c0, lid));
            ldsm4(ah[1], addrA(st,            wm * 32 + 16, c0, lid));
            ldsm4(al[0], addrA(st + ATILE_B,  wm * 32,      c0, lid));
            ldsm4(al[1], addrA(st + ATILE_B,  wm * 32 + 16, c0, lid));
            uint32_t w[4][8];
#pragma unroll
            for (int t = 0; t < 4; ++t) {
                ldsm4(&w[t][0], addrB(stW + t * WTILE_B, wn * 32,      c0, lid));
                ldsm4(&w[t][4], addrB(stW + t * WTILE_B, wn * 32 + 16, c0, lid));
            }
#pragma unroll
            for (int mi = 0; mi < 2; ++mi) {
#pragma unroll
                for (int ni = 0; ni < 4; ++ni) {
                    mma16816(acc1[mi][ni], ah[mi], &w[0][ni * 2]);   // Ah*W1h
                    mma16816(acc1[mi][ni], ah[mi], &w[1][ni * 2]);   // Ah*W1l
                    mma16816(acc1[mi][ni], al[mi], &w[0][ni * 2]);   // Al*W1h
                    mma16816(acc2[mi][ni], ah[mi], &w[2][ni * 2]);   // Ah*W2h
                    mma16816(acc2[mi][ni], ah[mi], &w[3][ni * 2]);   // Ah*W2l
                    mma16816(acc2[mi][ni], al[mi], &w[2][ni * 2]);   // Al*W2h
                }
            }
        }
        __syncthreads();
    }
    CP_WAIT0();

    // epilogue: bias + sigmoid + clamp + product
#pragma unroll
    for (int mi = 0; mi < 2; ++mi) {
        const int mrow = m0 + wm * 32 + mi * 16 + (lid >> 2);
#pragma unroll
        for (int ni = 0; ni < 4; ++ni) {
            const int col = n0 + wn * 32 + ni * 8 + (lid & 3) * 2;
            const float b1x = b1v[col], b1y = b1v[col + 1];
            const float b2x = b2v[col], b2y = b2v[col + 1];

            float h1, z, s;
            float2 r;
            h1 = clamp_small(acc1[mi][ni][0] + b1x);
            z  = acc2[mi][ni][0] + b2x;
            s  = clamp_small(1.0f / (1.0f + expf(-z)));
            r.x = h1 * s;
            h1 = clamp_small(acc1[mi][ni][1] + b1y);
            z  = acc2[mi][ni][1] + b2y;
            s  = clamp_small(1.0f / (1.0f + expf(-z)));
            r.y = h1 * s;
            *(float2*)(out + (size_t)mrow * DOUT + col) = r;

            h1 = clamp_small(acc1[mi][ni][2] + b1x);
            z  = acc2[mi][ni][2] + b2x;
            s  = clamp_small(1.0f / (1.0f + expf(-z)));
            r.x = h1 * s;
            h1 = clamp_small(acc1[mi][ni][3] + b1y);
            z  = acc2[mi][ni][3] + b2y;
            s  = clamp_small(1.0f / (1.0f + expf(-z)));
            r.y = h1 * s;
            *(float2*)(out + (size_t)(mrow + 8) * DOUT + col) = r;
        }
    }
}

// ---------------- launch ----------------
extern "C" void kernel_launch(void* const* d_in, const int* in_sizes, int n_in,
                              void* d_out, int out_size) {
    const float* x     = (const float*)d_in[0];
    const float* w1    = (const float*)d_in[1];
    const float* b1    = (const float*)d_in[2];
    const float* w2    = (const float*)d_in[3];
    const float* b2    = (const float*)d_in[4];
    const float* gamma = (const float*)d_in[5];
    const float* beta  = (const float*)d_in[6];
    float* out = (float*)d_out;

    cudaFuncSetAttribute(dual_gemm_mma, cudaFuncAttributeMaxDynamicSharedMemorySize,
                         SMEM_BYTES_G);

    colstats_partial<<<dim3(DK / 256, NROWS / 256), 256>>>(x);
    colstats_final<<<DK / 256, 256>>>(gamma, beta);
    convert_x_kernel<<<(NROWS * (DK / 8)) / 256, 256>>>(x);
    convert_w_kernel<<<(DOUT * (DK / 8)) / 256, 256>>>(w1, 0);
    convert_w_kernel<<<(DOUT * (DK / 8)) / 256, 256>>>(w2, 1);

    const int grid = (NROWS / BM) * (DOUT / BN);   // 4096
    dual_gemm_mma<<<grid, 256, SMEM_BYTES_G>>>(b1, b2, out);
}

// round 4
// speedup vs baseline: 4.2254x; 1.7118x over previous
#include <cuda_runtime.h>
#include <cuda_fp16.h>
#include <math.h>
#include <stdint.h>

#define NROWS 16384
#define DK    2048
#define DOUT  2048

// GEMM tiling
#define BM 128
#define BN 64
#define NST 4                  // pipeline stages
#define ATILE_B (BM * 64)      // 8192 B  (128 rows x 32 fp16 = 64B rows)
#define WTILE_B (BN * 64)      // 4096 B
#define STAGE_B (ATILE_B + 4 * WTILE_B)   // 24576
#define SMEM_BYTES_G (NST * STAGE_B)      // 98304
#define NSTAGES_K (DK / 32)    // 64

// ---------------- device scratch (no allocations allowed) ----------------
__device__ float g_psum[64][DK];
__device__ float g_psq [64][DK];
__device__ float g_scale[DK];
__device__ float g_shift[DK];

__device__ uint4 g_Ah [(size_t)NROWS * DK / 8];   // fp16, 64 MB
__device__ uint4 g_W1h[(size_t)DOUT * DK / 8];    // fp16, 8 MB each
__device__ uint4 g_W1l[(size_t)DOUT * DK / 8];
__device__ uint4 g_W2h[(size_t)DOUT * DK / 8];
__device__ uint4 g_W2l[(size_t)DOUT * DK / 8];

// ---------------- helpers ----------------
__device__ __forceinline__ uint32_t smem_u32(const void* p) {
    uint32_t a;
    asm("{ .reg .u64 t; cvta.to.shared.u64 t, %1; cvt.u32.u64 %0, t; }" : "=r"(a) : "l"(p));
    return a;
}
#define CP16(dst, src) \
    asm volatile("cp.async.cg.shared.global [%0], [%1], 16;" :: "r"(dst), "l"(src))
#define CP_COMMIT() asm volatile("cp.async.commit_group;" ::: "memory")
#define CP_WAIT2()  asm volatile("cp.async.wait_group 2;" ::: "memory")
#define CP_WAIT0()  asm volatile("cp.async.wait_group 0;" ::: "memory")

// swizzled offset inside a tile with 64B rows: 16B chunk XOR'ed by row bits
__device__ __forceinline__ uint32_t swz(int row, int c) {
    return (uint32_t)(row * 64 + ((c ^ ((row >> 1) & 3)) << 4));
}

__device__ __forceinline__ void ldsm4(uint32_t* r, uint32_t addr) {
    asm volatile("ldmatrix.sync.aligned.m8n8.x4.shared.b16 {%0,%1,%2,%3}, [%4];"
                 : "=r"(r[0]), "=r"(r[1]), "=r"(r[2]), "=r"(r[3]) : "r"(addr));
}

__device__ __forceinline__ void mma16816(float* d, const uint32_t* a, const uint32_t* b) {
    asm volatile(
        "mma.sync.aligned.m16n8k16.row.col.f32.f16.f16.f32 "
        "{%0,%1,%2,%3}, {%4,%5,%6,%7}, {%8,%9}, {%0,%1,%2,%3};"
        : "+f"(d[0]), "+f"(d[1]), "+f"(d[2]), "+f"(d[3])
        : "r"(a[0]), "r"(a[1]), "r"(a[2]), "r"(a[3]), "r"(b[0]), "r"(b[1]));
}

// A-style ldmatrix address: mat bit0 -> +8 rows, bit1 -> +k8 chunk
__device__ __forceinline__ uint32_t addrA(uint32_t tbase, int rowbase, int c0, int lid) {
    int m = lid >> 3, r8 = lid & 7;
    int row = rowbase + r8 + (m & 1) * 8;
    int ch  = c0 + (m >> 1);
    return tbase + swz(row, ch);
}
// B-style ldmatrix address: mat bit0 -> +k8 chunk, bit1 -> +8 rows
__device__ __forceinline__ uint32_t addrB(uint32_t tbase, int rowbase, int c0, int lid) {
    int m = lid >> 3, r8 = lid & 7;
    int row = rowbase + r8 + (m >> 1) * 8;
    int ch  = c0 + (m & 1);
    return tbase + swz(row, ch);
}

// ---------------- stats ----------------
__global__ void colstats_partial(const float* __restrict__ x) {
    int col = blockIdx.x * 256 + threadIdx.x;
    int r0  = blockIdx.y * 256;
    const float* p = x + (size_t)r0 * DK + col;
    float s = 0.f, ss = 0.f;
#pragma unroll 8
    for (int r = 0; r < 256; ++r) {
        float v = p[(size_t)r * DK];
        s += v; ss += v * v;
    }
    g_psum[blockIdx.y][col] = s;
    g_psq [blockIdx.y][col] = ss;
}

__global__ void colstats_final(const float* __restrict__ gamma,
                               const float* __restrict__ beta) {
    int col = blockIdx.x * 256 + threadIdx.x;
    float s = 0.f, ss = 0.f;
#pragma unroll
    for (int c = 0; c < 64; ++c) { s += g_psum[c][col]; ss += g_psq[c][col]; }
    float mean = s / (float)NROWS;
    float var  = (ss - s * mean) / (float)(NROWS - 1);   // ddof=1 (torch.std)
    float inv  = rsqrtf(var + 1e-8f);
    float sc   = gamma[col] * inv;
    g_scale[col] = sc;
    g_shift[col] = beta[col] - mean * sc;
}

// ---------------- fp16 conversions ----------------
__device__ __forceinline__ uint32_t pack2h(float a, float b) {
    __half2 h = __floats2half2_rn(a, b);
    return *reinterpret_cast<uint32_t*>(&h);
}

// x -> normalized fp16 (single precision term)
__global__ void convert_x_kernel(const float* __restrict__ x) {
    int i = blockIdx.x * 256 + threadIdx.x;            // uint4 index (8 elems)
    int col = (i * 8) & (DK - 1);
    const float4* xp = (const float4*)x + (size_t)i * 2;
    float4 v0 = xp[0], v1 = xp[1];
    float4 sc0 = *(const float4*)(g_scale + col);
    float4 sc1 = *(const float4*)(g_scale + col + 4);
    float4 sh0 = *(const float4*)(g_shift + col);
    float4 sh1 = *(const float4*)(g_shift + col + 4);
    float a[8] = {
        v0.x * sc0.x + sh0.x, v0.y * sc0.y + sh0.y,
        v0.z * sc0.z + sh0.z, v0.w * sc0.w + sh0.w,
        v1.x * sc1.x + sh1.x, v1.y * sc1.y + sh1.y,
        v1.z * sc1.z + sh1.z, v1.w * sc1.w + sh1.w };
    uint4 hi;
    hi.x = pack2h(a[0], a[1]);
    hi.y = pack2h(a[2], a[3]);
    hi.z = pack2h(a[4], a[5]);
    hi.w = pack2h(a[6], a[7]);
    g_Ah[i] = hi;
}

// w -> fp16 hi + fp16 residual
__global__ void convert_w_kernel(const float* __restrict__ w, int which) {
    int i = blockIdx.x * 256 + threadIdx.x;
    const float4* wp = (const float4*)w + (size_t)i * 2;
    float4 v0 = wp[0], v1 = wp[1];
    float a[8] = {v0.x, v0.y, v0.z, v0.w, v1.x, v1.y, v1.z, v1.w};
    float r[8];
#pragma unroll
    for (int j = 0; j < 8; ++j)
        r[j] = a[j] - __half2float(__float2half_rn(a[j]));
    uint4 hi, lo;
    hi.x = pack2h(a[0], a[1]); lo.x = pack2h(r[0], r[1]);
    hi.y = pack2h(a[2], a[3]); lo.y = pack2h(r[2], r[3]);
    hi.z = pack2h(a[4], a[5]); lo.z = pack2h(r[4], r[5]);
    hi.w = pack2h(a[6], a[7]); lo.w = pack2h(r[6], r[7]);
    if (which == 0) { g_W1h[i] = hi; g_W1l[i] = lo; }
    else            { g_W2h[i] = hi; g_W2l[i] = lo; }
}

__device__ __forceinline__ float clamp_small(float t) {
    const float EPS = 1e-12f;
    if (t >= 0.f && t <  EPS) return  EPS;
    if (t <  0.f && t > -EPS) return -EPS;
    return t;
}

// ---------------- fused dual GEMM (mma.sync fp16, 2-term split-W) ----------------
__global__ __launch_bounds__(256, 2)
void dual_gemm_mma(const float* __restrict__ b1v, const float* __restrict__ b2v,
                   float* __restrict__ out) {
    extern __shared__ __align__(128) char smem[];
    const uint32_t sbase = smem_u32(smem);

    const int tid = threadIdx.x;
    const int lid = tid & 31;
    const int wid = tid >> 5;
    const int wm  = wid & 3;        // 4 warps along M
    const int wn  = wid >> 2;       // 2 warps along N

    // rasterize: 8 n-tiles per group, m fastest -> wave shares A rows & W cols in L2
    const int id  = blockIdx.x;
    const int grp = id >> 10;
    const int rem = id & 1023;
    const int m0  = (rem >> 3) * BM;
    const int n0  = ((grp << 3) | (rem & 7)) * BN;

    const char* srcA = (const char*)g_Ah + (size_t)m0 * 4096;
    const char* srcW[4] = { (const char*)g_W1h + (size_t)n0 * 4096,
                            (const char*)g_W1l + (size_t)n0 * 4096,
                            (const char*)g_W2h + (size_t)n0 * 4096,
                            (const char*)g_W2l + (size_t)n0 * 4096 };

    const int arow0 = tid >> 2;        // 0..63, A covers 128 rows in two passes
    const int ac    = tid & 3;

    auto issue = [&](int bi, int kb) {
        const uint32_t st = sbase + bi * STAGE_B;
#pragma unroll
        for (int j = 0; j < 2; ++j) {
            int row = arow0 + 64 * j;
            CP16(st + swz(row, ac), srcA + (size_t)row * 4096 + kb + ac * 16);
        }
        uint32_t d = st + ATILE_B + swz(arow0, ac);
        const size_t off = (size_t)arow0 * 4096 + kb + ac * 16;
        CP16(d,               srcW[0] + off);
        CP16(d + WTILE_B,     srcW[1] + off);
        CP16(d + 2 * WTILE_B, srcW[2] + off);
        CP16(d + 3 * WTILE_B, srcW[3] + off);
    };

    float acc1[2][4][4];
    float acc2[2][4][4];
#pragma unroll
    for (int mi = 0; mi < 2; ++mi)
#pragma unroll
        for (int ni = 0; ni < 4; ++ni)
#pragma unroll
            for (int j = 0; j < 4; ++j) { acc1[mi][ni][j] = 0.f; acc2[mi][ni][j] = 0.f; }

    issue(0, 0);   CP_COMMIT();
    issue(1, 64);  CP_COMMIT();
    issue(2, 128); CP_COMMIT();

    for (int i = 0; i < NSTAGES_K; ++i) {
        CP_WAIT2();
        __syncthreads();
        if (i + 3 < NSTAGES_K) issue((i + 3) & 3, (i + 3) * 64);
        CP_COMMIT();

        const uint32_t st  = sbase + (i & 3) * STAGE_B;
        const uint32_t stW = st + ATILE_B;
#pragma unroll
        for (int ks = 0; ks < 2; ++ks) {
            const int c0 = ks * 2;
            uint32_t ah[2][4];
            ldsm4(ah[0], addrA(st, wm * 32,      c0, lid));
            ldsm4(ah[1], addrA(st, wm * 32 + 16, c0, lid));
            uint32_t w[4][8];
#pragma unroll
            for (int t = 0; t < 4; ++t) {
                ldsm4(&w[t][0], addrB(stW + t * WTILE_B, wn * 32,      c0, lid));
                ldsm4(&w[t][4], addrB(stW + t * WTILE_B, wn * 32 + 16, c0, lid));
            }
#pragma unroll
            for (int mi = 0; mi < 2; ++mi) {
#pragma unroll
                for (int ni = 0; ni < 4; ++ni) {
                    mma16816(acc1[mi][ni], ah[mi], &w[0][ni * 2]);   // Ah*W1h
                    mma16816(acc1[mi][ni], ah[mi], &w[1][ni * 2]);   // Ah*W1l
                    mma16816(acc2[mi][ni], ah[mi], &w[2][ni * 2]);   // Ah*W2h
                    mma16816(acc2[mi][ni], ah[mi], &w[3][ni * 2]);   // Ah*W2l
                }
            }
        }
        __syncthreads();
    }
    CP_WAIT0();

    // epilogue: bias + sigmoid + clamp + product
#pragma unroll
    for (int mi = 0; mi < 2; ++mi) {
        const int mrow = m0 + wm * 32 + mi * 16 + (lid >> 2);
#pragma unroll
        for (int ni = 0; ni < 4; ++ni) {
            const int col = n0 + wn * 32 + ni * 8 + (lid & 3) * 2;
            const float b1x = b1v[col], b1y = b1v[col + 1];
            const float b2x = b2v[col], b2y = b2v[col + 1];

            float h1, z, s;
            float2 r;
            h1 = clamp_small(acc1[mi][ni][0] + b1x);
            z  = acc2[mi][ni][0] + b2x;
            s  = clamp_small(1.0f / (1.0f + expf(-z)));
            r.x = h1 * s;
            h1 = clamp_small(acc1[mi][ni][1] + b1y);
            z  = acc2[mi][ni][1] + b2y;
            s  = clamp_small(1.0f / (1.0f + expf(-z)));
            r.y = h1 * s;
            *(float2*)(out + (size_t)mrow * DOUT + col) = r;

            h1 = clamp_small(acc1[mi][ni][2] + b1x);
            z  = acc2[mi][ni][2] + b2x;
            s  = clamp_small(1.0f / (1.0f + expf(-z)));
            r.x = h1 * s;
            h1 = clamp_small(acc1[mi][ni][3] + b1y);
            z  = acc2[mi][ni][3] + b2y;
            s  = clamp_small(1.0f / (1.0f + expf(-z)));
            r.y = h1 * s;
            *(float2*)(out + (size_t)(mrow + 8) * DOUT + col) = r;
        }
    }
}

// ---------------- launch ----------------
extern "C" void kernel_launch(void* const* d_in, const int* in_sizes, int n_in,
                              void* d_out, int out_size) {
    const float* x     = (const float*)d_in[0];
    const float* w1    = (const float*)d_in[1];
    const float* b1    = (const float*)d_in[2];
    const float* w2    = (const float*)d_in[3];
    const float* b2    = (const float*)d_in[4];
    const float* gamma = (const float*)d_in[5];
    const float* beta  = (const float*)d_in[6];
    float* out = (float*)d_out;

    cudaFuncSetAttribute(dual_gemm_mma, cudaFuncAttributeMaxDynamicSharedMemorySize,
                         SMEM_BYTES_G);

    colstats_partial<<<dim3(DK / 256, NROWS / 256), 256>>>(x);
    colstats_final<<<DK / 256, 256>>>(gamma, beta);
    convert_x_kernel<<<(NROWS * (DK / 8)) / 256, 256>>>(x);
    convert_w_kernel<<<(DOUT * (DK / 8)) / 256, 256>>>(w1, 0);
    convert_w_kernel<<<(DOUT * (DK / 8)) / 256, 256>>>(w2, 1);

    const int grid = (NROWS / BM) * (DOUT / BN);   // 4096
    dual_gemm_mma<<<grid, 256, SMEM_BYTES_G>>>(b1, b2, out);
}

// round 5
// speedup vs baseline: 7.2138x; 1.7072x over previous
#include <cuda_runtime.h>
#include <cuda_fp16.h>
#include <math.h>
#include <stdint.h>

#define NROWS 16384
#define DK    2048
#define DOUT  2048

// GEMM tiling
#define BM 128
#define BN 64
#define NST 4                  // pipeline stages
#define ATILE_B (BM * 64)      // 8192 B  (128 rows x 32 fp16 = 64B rows)
#define WTILE_B (BN * 64)      // 4096 B
#define STAGE_B (ATILE_B + 2 * WTILE_B)   // 16384
#define SMEM_BYTES_G (NST * STAGE_B)      // 65536
#define NSTAGES_K (DK / 32)    // 64

// ---------------- device scratch (no allocations allowed) ----------------
__device__ float g_psum[64][DK];
__device__ float g_psq [64][DK];
__device__ float g_scale[DK];
__device__ float g_shift[DK];

__device__ uint4 g_Ah [(size_t)NROWS * DK / 8];   // fp16 normalized x, 64 MB
__device__ uint4 g_W1h[(size_t)DOUT * DK / 8];    // fp16 weights, 8 MB each
__device__ uint4 g_W2h[(size_t)DOUT * DK / 8];

// ---------------- helpers ----------------
__device__ __forceinline__ uint32_t smem_u32(const void* p) {
    uint32_t a;
    asm("{ .reg .u64 t; cvta.to.shared.u64 t, %1; cvt.u32.u64 %0, t; }" : "=r"(a) : "l"(p));
    return a;
}
#define CP16(dst, src) \
    asm volatile("cp.async.cg.shared.global [%0], [%1], 16;" :: "r"(dst), "l"(src))
#define CP_COMMIT() asm volatile("cp.async.commit_group;" ::: "memory")
#define CP_WAIT2()  asm volatile("cp.async.wait_group 2;" ::: "memory")
#define CP_WAIT0()  asm volatile("cp.async.wait_group 0;" ::: "memory")

// swizzled offset inside a tile with 64B rows: 16B chunk XOR'ed by row bits
__device__ __forceinline__ uint32_t swz(int row, int c) {
    return (uint32_t)(row * 64 + ((c ^ ((row >> 1) & 3)) << 4));
}

__device__ __forceinline__ void ldsm4(uint32_t* r, uint32_t addr) {
    asm volatile("ldmatrix.sync.aligned.m8n8.x4.shared.b16 {%0,%1,%2,%3}, [%4];"
                 : "=r"(r[0]), "=r"(r[1]), "=r"(r[2]), "=r"(r[3]) : "r"(addr));
}

__device__ __forceinline__ void mma16816(float* d, const uint32_t* a, const uint32_t* b) {
    asm volatile(
        "mma.sync.aligned.m16n8k16.row.col.f32.f16.f16.f32 "
        "{%0,%1,%2,%3}, {%4,%5,%6,%7}, {%8,%9}, {%0,%1,%2,%3};"
        : "+f"(d[0]), "+f"(d[1]), "+f"(d[2]), "+f"(d[3])
        : "r"(a[0]), "r"(a[1]), "r"(a[2]), "r"(a[3]), "r"(b[0]), "r"(b[1]));
}

// A-style ldmatrix address: mat bit0 -> +8 rows, bit1 -> +k8 chunk
__device__ __forceinline__ uint32_t addrA(uint32_t tbase, int rowbase, int c0, int lid) {
    int m = lid >> 3, r8 = lid & 7;
    int row = rowbase + r8 + (m & 1) * 8;
    int ch  = c0 + (m >> 1);
    return tbase + swz(row, ch);
}
// B-style ldmatrix address: mat bit0 -> +k8 chunk, bit1 -> +8 rows
__device__ __forceinline__ uint32_t addrB(uint32_t tbase, int rowbase, int c0, int lid) {
    int m = lid >> 3, r8 = lid & 7;
    int row = rowbase + r8 + (m >> 1) * 8;
    int ch  = c0 + (m & 1);
    return tbase + swz(row, ch);
}

// ---------------- stats ----------------
__global__ void colstats_partial(const float* __restrict__ x) {
    int col = blockIdx.x * 256 + threadIdx.x;
    int r0  = blockIdx.y * 256;
    const float* p = x + (size_t)r0 * DK + col;
    float s = 0.f, ss = 0.f;
#pragma unroll 8
    for (int r = 0; r < 256; ++r) {
        float v = p[(size_t)r * DK];
        s += v; ss += v * v;
    }
    g_psum[blockIdx.y][col] = s;
    g_psq [blockIdx.y][col] = ss;
}

__global__ void colstats_final(const float* __restrict__ gamma,
                               const float* __restrict__ beta) {
    int col = blockIdx.x * 256 + threadIdx.x;
    float s = 0.f, ss = 0.f;
#pragma unroll
    for (int c = 0; c < 64; ++c) { s += g_psum[c][col]; ss += g_psq[c][col]; }
    float mean = s / (float)NROWS;
    float var  = (ss - s * mean) / (float)(NROWS - 1);   // ddof=1 (torch.std)
    float inv  = rsqrtf(var + 1e-8f);
    float sc   = gamma[col] * inv;
    g_scale[col] = sc;
    g_shift[col] = beta[col] - mean * sc;
}

// ---------------- fp16 conversions ----------------
__device__ __forceinline__ uint32_t pack2h(float a, float b) {
    __half2 h = __floats2half2_rn(a, b);
    return *reinterpret_cast<uint32_t*>(&h);
}

// x -> normalized fp16
__global__ void convert_x_kernel(const float* __restrict__ x) {
    int i = blockIdx.x * 256 + threadIdx.x;            // uint4 index (8 elems)
    int col = (i * 8) & (DK - 1);
    const float4* xp = (const float4*)x + (size_t)i * 2;
    float4 v0 = xp[0], v1 = xp[1];
    float4 sc0 = *(const float4*)(g_scale + col);
    float4 sc1 = *(const float4*)(g_scale + col + 4);
    float4 sh0 = *(const float4*)(g_shift + col);
    float4 sh1 = *(const float4*)(g_shift + col + 4);
    uint4 hi;
    hi.x = pack2h(v0.x * sc0.x + sh0.x, v0.y * sc0.y + sh0.y);
    hi.y = pack2h(v0.z * sc0.z + sh0.z, v0.w * sc0.w + sh0.w);
    hi.z = pack2h(v1.x * sc1.x + sh1.x, v1.y * sc1.y + sh1.y);
    hi.w = pack2h(v1.z * sc1.z + sh1.z, v1.w * sc1.w + sh1.w);
    g_Ah[i] = hi;
}

// w -> fp16 (both weights in one pass)
__global__ void convert_w_kernel(const float* __restrict__ w1,
                                 const float* __restrict__ w2) {
    int i = blockIdx.x * 256 + threadIdx.x;
    const float4* wp1 = (const float4*)w1 + (size_t)i * 2;
    const float4* wp2 = (const float4*)w2 + (size_t)i * 2;
    float4 a0 = wp1[0], a1 = wp1[1];
    float4 b0 = wp2[0], b1 = wp2[1];
    uint4 h1, h2;
    h1.x = pack2h(a0.x, a0.y); h1.y = pack2h(a0.z, a0.w);
    h1.z = pack2h(a1.x, a1.y); h1.w = pack2h(a1.z, a1.w);
    h2.x = pack2h(b0.x, b0.y); h2.y = pack2h(b0.z, b0.w);
    h2.z = pack2h(b1.x, b1.y); h2.w = pack2h(b1.z, b1.w);
    g_W1h[i] = h1;
    g_W2h[i] = h2;
}

__device__ __forceinline__ float clamp_small(float t) {
    const float EPS = 1e-12f;
    if (t >= 0.f && t <  EPS) return  EPS;
    if (t <  0.f && t > -EPS) return -EPS;
    return t;
}

// ---------------- fused dual GEMM (plain fp16 mma.sync) ----------------
__global__ __launch_bounds__(256, 2)
void dual_gemm_mma(const float* __restrict__ b1v, const float* __restrict__ b2v,
                   float* __restrict__ out) {
    extern __shared__ __align__(128) char smem[];
    const uint32_t sbase = smem_u32(smem);

    const int tid = threadIdx.x;
    const int lid = tid & 31;
    const int wid = tid >> 5;
    const int wm  = wid & 3;        // 4 warps along M
    const int wn  = wid >> 2;       // 2 warps along N

    // rasterize: 8 n-tiles per group, m fastest -> wave shares A rows & W cols in L2
    const int id  = blockIdx.x;
    const int grp = id >> 10;
    const int rem = id & 1023;
    const int m0  = (rem >> 3) * BM;
    const int n0  = ((grp << 3) | (rem & 7)) * BN;

    const char* srcA = (const char*)g_Ah + (size_t)m0 * 4096;
    const char* srcW1 = (const char*)g_W1h + (size_t)n0 * 4096;
    const char* srcW2 = (const char*)g_W2h + (size_t)n0 * 4096;

    const int arow0 = tid >> 2;        // 0..63, A covers 128 rows in two passes
    const int ac    = tid & 3;

    auto issue = [&](int bi, int kb) {
        const uint32_t st = sbase + bi * STAGE_B;
#pragma unroll
        for (int j = 0; j < 2; ++j) {
            int row = arow0 + 64 * j;
            CP16(st + swz(row, ac), srcA + (size_t)row * 4096 + kb + ac * 16);
        }
        uint32_t d = st + ATILE_B + swz(arow0, ac);
        const size_t off = (size_t)arow0 * 4096 + kb + ac * 16;
        CP16(d,           srcW1 + off);
        CP16(d + WTILE_B, srcW2 + off);
    };

    float acc1[2][4][4];
    float acc2[2][4][4];
#pragma unroll
    for (int mi = 0; mi < 2; ++mi)
#pragma unroll
        for (int ni = 0; ni < 4; ++ni)
#pragma unroll
            for (int j = 0; j < 4; ++j) { acc1[mi][ni][j] = 0.f; acc2[mi][ni][j] = 0.f; }

    issue(0, 0);   CP_COMMIT();
    issue(1, 64);  CP_COMMIT();
    issue(2, 128); CP_COMMIT();

    for (int i = 0; i < NSTAGES_K; ++i) {
        CP_WAIT2();
        __syncthreads();
        if (i + 3 < NSTAGES_K) issue((i + 3) & 3, (i + 3) * 64);
        CP_COMMIT();

        const uint32_t st  = sbase + (i & 3) * STAGE_B;
        const uint32_t stW = st + ATILE_B;
#pragma unroll
        for (int ks = 0; ks < 2; ++ks) {
            const int c0 = ks * 2;
            uint32_t ah[2][4];
            ldsm4(ah[0], addrA(st, wm * 32,      c0, lid));
            ldsm4(ah[1], addrA(st, wm * 32 + 16, c0, lid));
            uint32_t w[2][8];
#pragma unroll
            for (int t = 0; t < 2; ++t) {
                ldsm4(&w[t][0], addrB(stW + t * WTILE_B, wn * 32,      c0, lid));
                ldsm4(&w[t][4], addrB(stW + t * WTILE_B, wn * 32 + 16, c0, lid));
            }
#pragma unroll
            for (int mi = 0; mi < 2; ++mi) {
#pragma unroll
                for (int ni = 0; ni < 4; ++ni) {
                    mma16816(acc1[mi][ni], ah[mi], &w[0][ni * 2]);   // A*W1
                    mma16816(acc2[mi][ni], ah[mi], &w[1][ni * 2]);   // A*W2
                }
            }
        }
        __syncthreads();
    }
    CP_WAIT0();

    // epilogue: bias + sigmoid + clamp + product
#pragma unroll
    for (int mi = 0; mi < 2; ++mi) {
        const int mrow = m0 + wm * 32 + mi * 16 + (lid >> 2);
#pragma unroll
        for (int ni = 0; ni < 4; ++ni) {
            const int col = n0 + wn * 32 + ni * 8 + (lid & 3) * 2;
            const float b1x = b1v[col], b1y = b1v[col + 1];
            const float b2x = b2v[col], b2y = b2v[col + 1];

            float h1, z, s;
            float2 r;
            h1 = clamp_small(acc1[mi][ni][0] + b1x);
            z  = acc2[mi][ni][0] + b2x;
            s  = clamp_small(1.0f / (1.0f + expf(-z)));
            r.x = h1 * s;
            h1 = clamp_small(acc1[mi][ni][1] + b1y);
            z  = acc2[mi][ni][1] + b2y;
            s  = clamp_small(1.0f / (1.0f + expf(-z)));
            r.y = h1 * s;
            *(float2*)(out + (size_t)mrow * DOUT + col) = r;

            h1 = clamp_small(acc1[mi][ni][2] + b1x);
            z  = acc2[mi][ni][2] + b2x;
            s  = clamp_small(1.0f / (1.0f + expf(-z)));
            r.x = h1 * s;
            h1 = clamp_small(acc1[mi][ni][3] + b1y);
            z  = acc2[mi][ni][3] + b2y;
            s  = clamp_small(1.0f / (1.0f + expf(-z)));
            r.y = h1 * s;
            *(float2*)(out + (size_t)(mrow + 8) * DOUT + col) = r;
        }
    }
}

// ---------------- launch ----------------
extern "C" void kernel_launch(void* const* d_in, const int* in_sizes, int n_in,
                              void* d_out, int out_size) {
    const float* x     = (const float*)d_in[0];
    const float* w1    = (const float*)d_in[1];
    const float* b1    = (const float*)d_in[2];
    const float* w2    = (const float*)d_in[3];
    const float* b2    = (const float*)d_in[4];
    const float* gamma = (const float*)d_in[5];
    const float* beta  = (const float*)d_in[6];
    float* out = (float*)d_out;

    cudaFuncSetAttribute(dual_gemm_mma, cudaFuncAttributeMaxDynamicSharedMemorySize,
                         SMEM_BYTES_G);

    colstats_partial<<<dim3(DK / 256, NROWS / 256), 256>>>(x);
    colstats_final<<<DK / 256, 256>>>(gamma, beta);
    convert_x_kernel<<<(NROWS * (DK / 8)) / 256, 256>>>(x);
    convert_w_kernel<<<(DOUT * (DK / 8)) / 256, 256>>>(w1, w2);

    const int grid = (NROWS / BM) * (DOUT / BN);   // 4096
    dual_gemm_mma<<<grid, 256, SMEM_BYTES_G>>>(b1, b2, out);
}